// round 9
// baseline (speedup 1.0000x reference)
#include <cuda_runtime.h>
#include <math.h>

#define H 1024
#define L 128
#define V 50257
#define FNB 444              // 3 blocks/SM * 148 SMs — all co-resident
#define FNT 256
#define LNB 296              // 2 blocks/SM — co-resident for epilogue barrier
#define LNT 256

// ---- scratch (device globals; no allocation allowed) ----
__device__ __align__(16) float g_attn_logits[L];
__device__ __align__(16) float g_with_attn[H];
__device__ __align__(16) float g_rnn_in[H];
__device__ __align__(16) float g_gh[3 * H];      // W_hh @ h0 + b_hh (hoisted)
__device__ __align__(16) float g_gx[3 * H];      // W_ih @ rnn_in + b_ih
__device__ __align__(16) float g_hnew[H];
__device__ __align__(16) float g_logits[V];
__device__ float g_sumexp;
__device__ unsigned int g_cnt[5];
__device__ volatile unsigned int g_flag[5];

__device__ __forceinline__ float warp_sum(float v) {
#pragma unroll
    for (int o = 16; o > 0; o >>= 1) v += __shfl_xor_sync(0xffffffffu, v, o);
    return v;
}

__device__ __forceinline__ float dot4(float4 a, float4 b) {
    return a.x * b.x + a.y * b.y + a.z * b.z + a.w * b.w;
}

__device__ __forceinline__ void grid_bar(int i, unsigned int my_sense, int nb, int t) {
    __syncthreads();
    if (t == 0) {
        __threadfence();
        unsigned int old = atomicAdd(&g_cnt[i], 1u);
        if (old == (unsigned int)(nb - 1)) {
            g_cnt[i] = 0u;
            __threadfence();
            g_flag[i] = my_sense ^ 1u;
        } else {
            while (g_flag[i] == my_sense) { }
        }
        __threadfence();
    }
    __syncthreads();
}

// ===== K1: fused front =====
__global__ void __launch_bounds__(FNT, 3) k_front(
    const int* __restrict__ x,
    const float* __restrict__ hidden,
    const float* __restrict__ enc,
    const float* __restrict__ emb,
    const float* __restrict__ attn_W,
    const float* __restrict__ attn_b,
    const float* __restrict__ comb_W,
    const float* __restrict__ comb_b,
    const float* __restrict__ W_ih,
    const float* __restrict__ W_hh,
    const float* __restrict__ b_ih,
    const float* __restrict__ b_hh,
    float* __restrict__ out)
{
    __shared__ unsigned int sense[4];
    __shared__ float sw[L];
    __shared__ float redm[4], reds[4];
    __shared__ float sp[8];

    int t = threadIdx.x;
    int b = blockIdx.x;
    int w = t >> 5;
    int lane = t & 31;
    int gw = b * 8 + w;

    if (t < 4) sense[t] = g_flag[t];
    __syncthreads();

    const float* erow = emb + (long long)x[0] * H;

    // ---- P0: attn logits (tasks 0..127) + gh (tasks 128..3199) + init ----
    if (b == FNB - 1) {
        *(float4*)(g_with_attn + t * 4) = make_float4(0.f, 0.f, 0.f, 0.f);
        if (t == 0) g_sumexp = 0.f;
    }
    if (gw < 3200) {
        if (gw < 128) {
            const float* wrow = attn_W + (long long)gw * 2 * H;
            float4 a[8];
            float acc = 0.f;
#pragma unroll
            for (int k = 0; k < 8; k++) a[k] = __ldcs((const float4*)(wrow + k * 128 + lane * 4));
#pragma unroll
            for (int k = 0; k < 8; k++) acc += dot4(a[k], *(const float4*)(erow + k * 128 + lane * 4));
#pragma unroll
            for (int k = 0; k < 8; k++) a[k] = __ldcs((const float4*)(wrow + H + k * 128 + lane * 4));
#pragma unroll
            for (int k = 0; k < 8; k++) acc += dot4(a[k], *(const float4*)(hidden + k * 128 + lane * 4));
            acc = warp_sum(acc);
            if (lane == 0) g_attn_logits[gw] = acc + attn_b[gw];
        } else {
            int r = gw - 128;      // 0..3071
            const float* wrow = W_hh + (long long)r * H;
            float4 a[8];
#pragma unroll
            for (int k = 0; k < 8; k++) a[k] = __ldcs((const float4*)(wrow + k * 128 + lane * 4));
            float acc = 0.f;
#pragma unroll
            for (int k = 0; k < 8; k++) acc += dot4(a[k], *(const float4*)(hidden + k * 128 + lane * 4));
            acc = warp_sum(acc);
            if (lane == 0) g_gh[r] = acc + b_hh[r];
        }
    }
    grid_bar(0, sense[0], FNB, t);

    // ---- P1: softmax (recomputed per block) + with_attention ----
    if (b < 128) {
        float v = 0.f;
        if (t < L) {
            v = g_attn_logits[t];
            float m = v;
#pragma unroll
            for (int o = 16; o > 0; o >>= 1) m = fmaxf(m, __shfl_xor_sync(0xffffffffu, m, o));
            if (lane == 0) redm[t >> 5] = m;
        }
        __syncthreads();
        float m4 = fmaxf(fmaxf(redm[0], redm[1]), fmaxf(redm[2], redm[3]));
        if (t < L) {
            float e = expf(v - m4);
            float ss = warp_sum(e);
            if (lane == 0) reds[t >> 5] = ss;
            sw[t] = e;
        }
        __syncthreads();
        float tot = (reds[0] + reds[1]) + (reds[2] + reds[3]);
        if (t < L) {
            sw[t] = sw[t] / tot;
            if (b == 0) out[V + H + t] = sw[t];
        }
        __syncthreads();
        int col = (b & 3) * 256 + t;   // 4 col chunks
        int l0 = (b >> 2) * 4;         // 32 row chunks of 4
        float acc = 0.f;
#pragma unroll
        for (int j = 0; j < 4; j++) acc += sw[l0 + j] * __ldg(enc + (l0 + j) * H + col);
        atomicAdd(&g_with_attn[col], acc);
    }
    grid_bar(1, sense[1], FNB, t);

    // ---- P2: rnn_in. Warp-pair per row: even warp = emb half, odd = attn half ----
    if (gw < 2 * H) {
        int row = gw >> 1;
        int half = gw & 1;
        const float* wrow = comb_W + (long long)row * 2 * H + half * H;
        const float* vec = half ? g_with_attn : erow;
        float4 a[8];
#pragma unroll
        for (int k = 0; k < 8; k++) a[k] = __ldcs((const float4*)(wrow + k * 128 + lane * 4));
        float acc = 0.f;
#pragma unroll
        for (int k = 0; k < 8; k++) acc += dot4(a[k], *(const float4*)(vec + k * 128 + lane * 4));
        acc = warp_sum(acc);
        if (lane == 0) sp[w] = acc;
    }
    __syncthreads();
    if (gw < 2 * H && (w & 1) == 0 && lane == 0) {
        int row = gw >> 1;
        g_rnn_in[row] = fmaxf(sp[w] + sp[w + 1] + comb_b[row], 0.f);
    }
    grid_bar(2, sense[2], FNB, t);

    // ---- P3: gx[r] = W_ih[r] . rnn_in + b_ih[r], warp per row (3072 warps) ----
    if (gw < 3 * H) {
        const float* wrow = W_ih + (long long)gw * H;
        float4 a[8];
#pragma unroll
        for (int k = 0; k < 8; k++) a[k] = __ldcs((const float4*)(wrow + k * 128 + lane * 4));
        float acc = 0.f;
#pragma unroll
        for (int k = 0; k < 8; k++) acc += dot4(a[k], *(const float4*)(g_rnn_in + k * 128 + lane * 4));
        acc = warp_sum(acc);
        if (lane == 0) g_gx[gw] = acc + b_ih[gw];
    }
    grid_bar(3, sense[3], FNB, t);

    // ---- P4: elementwise GRU combine (first 4 blocks) ----
    if (b < 4) {
        int i = b * 256 + t;
        float r = 1.f / (1.f + expf(-(g_gx[i] + g_gh[i])));
        float z = 1.f / (1.f + expf(-(g_gx[H + i] + g_gh[H + i])));
        float n = tanhf(g_gx[2 * H + i] + r * g_gh[2 * H + i]);
        float h = (1.f - z) * n + z * hidden[i];
        g_hnew[i] = h;
        out[V + i] = h;
    }
}

// ===== K2: persistent vocab GEMV + fused sum-exp + log-softmax writeout =====
__global__ void __launch_bounds__(LNT, 2) k_logits(const float* __restrict__ out_W,
                                                   const float* __restrict__ out_b,
                                                   float* __restrict__ out) {
    __shared__ float s_se[8];
    __shared__ unsigned int sense4;
    int t = threadIdx.x;
    int lane = t & 31;
    int w = t >> 5;
    int warp = (blockIdx.x * LNT + t) >> 5;
    const int nwarps = (LNB * LNT) >> 5;
    if (t == 0) sense4 = g_flag[4];
    __syncthreads();
    unsigned int my_sense = sense4;

    float4 h[8];
#pragma unroll
    for (int k = 0; k < 8; k++)
        h[k] = *(const float4*)(g_hnew + k * 128 + lane * 4);
    float se = 0.f;
    for (int v0 = warp * 2; v0 < V - 1; v0 += nwarps * 2) {
        const float* row0 = out_W + (long long)v0 * H + lane * 4;
        const float* row1 = row0 + H;
        float4 a0[8], a1[8];
#pragma unroll
        for (int k = 0; k < 8; k++) a0[k] = __ldcs((const float4*)(row0 + k * 128));
#pragma unroll
        for (int k = 0; k < 8; k++) a1[k] = __ldcs((const float4*)(row1 + k * 128));
        float acc0 = 0.f, acc1 = 0.f;
#pragma unroll
        for (int k = 0; k < 8; k++) {
            acc0 += dot4(a0[k], h[k]);
            acc1 += dot4(a1[k], h[k]);
        }
        acc0 = warp_sum(acc0);
        acc1 = warp_sum(acc1);
        if (lane == 0) {
            float lg0 = acc0 + out_b[v0];
            float lg1 = acc1 + out_b[v0 + 1];
            g_logits[v0] = lg0;
            g_logits[v0 + 1] = lg1;
            se += expf(lg0) + expf(lg1);
        }
    }
    if (warp == 0) {   // tail: last row (V odd)
        int v = V - 1;
        const float* row = out_W + (long long)v * H + lane * 4;
        float acc = 0.f;
#pragma unroll
        for (int k = 0; k < 8; k++)
            acc += dot4(__ldcs((const float4*)(row + k * 128)), h[k]);
        acc = warp_sum(acc);
        if (lane == 0) {
            float lg = acc + out_b[v];
            g_logits[v] = lg;
            se += expf(lg);
        }
    }
    if (lane == 0) s_se[w] = se;
    __syncthreads();
    if (t == 0) {
        float tot = 0.f;
#pragma unroll
        for (int k = 0; k < 8; k++) tot += s_se[k];
        atomicAdd(&g_sumexp, tot);
    }
    // grid barrier (all 296 blocks co-resident), then writeout
    grid_bar(4, my_sense, LNB, t);
    float lse = logf(g_sumexp);
    for (int v = blockIdx.x * LNT + t; v < V; v += LNB * LNT)
        out[v] = g_logits[v] - lse;
}

extern "C" void kernel_launch(void* const* d_in, const int* in_sizes, int n_in,
                              void* d_out, int out_size) {
    const int*   x       = (const int*)d_in[0];
    const float* hidden  = (const float*)d_in[1];
    const float* enc     = (const float*)d_in[2];
    const float* emb     = (const float*)d_in[3];
    const float* attn_W  = (const float*)d_in[4];
    const float* attn_b  = (const float*)d_in[5];
    const float* comb_W  = (const float*)d_in[6];
    const float* comb_b  = (const float*)d_in[7];
    const float* W_ih    = (const float*)d_in[8];
    const float* W_hh    = (const float*)d_in[9];
    const float* b_ih    = (const float*)d_in[10];
    const float* b_hh    = (const float*)d_in[11];
    const float* out_W   = (const float*)d_in[12];
    const float* out_b   = (const float*)d_in[13];
    float* out = (float*)d_out;   // layout: [logp V][h_new H][attn_w L]

    k_front<<<FNB, FNT>>>(x, hidden, enc, emb, attn_W, attn_b, comb_W, comb_b,
                          W_ih, W_hh, b_ih, b_hh, out);
    k_logits<<<LNB, LNT>>>(out_W, out_b, out);
}

// round 10
// speedup vs baseline: 1.1494x; 1.1494x over previous
#include <cuda_runtime.h>
#include <math.h>

#define H 1024
#define L 128
#define V 50257

// ---- scratch (device globals; no allocation allowed) ----
__device__ __align__(16) float g_attn_logits[L];
__device__ __align__(16) float g_with_attn[H];
__device__ __align__(16) float g_rnn_in[H];
__device__ __align__(16) float g_hnew[H];
__device__ __align__(16) float g_logits[V];
__device__ unsigned int g_max_enc;   // ordered-uint encoded max
__device__ float g_sumexp;
__device__ int g_bar;

__device__ __forceinline__ float warp_sum(float v) {
#pragma unroll
    for (int o = 16; o > 0; o >>= 1) v += __shfl_xor_sync(0xffffffffu, v, o);
    return v;
}

__device__ __forceinline__ float dot4(float4 a, float4 b) {
    return a.x * b.x + a.y * b.y + a.z * b.z + a.w * b.w;
}

// encode float so unsigned compare == float compare
__device__ __forceinline__ unsigned int enc_f(float f) {
    unsigned int u = __float_as_uint(f);
    return (u & 0x80000000u) ? ~u : (u | 0x80000000u);
}
__device__ __forceinline__ float dec_f(unsigned int u) {
    return (u & 0x80000000u) ? __uint_as_float(u ^ 0x80000000u)
                             : __uint_as_float(~u);
}

// ---- K1: attention logits (blocks 0..127) + init (block 128) ----
__global__ void __launch_bounds__(256) k_attn_logits(const int* __restrict__ x,
                              const float* __restrict__ hidden,
                              const float* __restrict__ emb,
                              const float* __restrict__ attn_W,
                              const float* __restrict__ attn_b) {
    int l = blockIdx.x;
    int t = threadIdx.x;         // 0..255
    if (l == 128) {              // init block: zero with_attn, reset scalars
        *(float4*)(g_with_attn + t * 4) = make_float4(0.f, 0.f, 0.f, 0.f);
        if (t == 0) { g_max_enc = 0u; g_sumexp = 0.f; g_bar = 0; }
        return;
    }
    const float* erow = emb + (long long)x[0] * H;
    const float* wrow = attn_W + (long long)l * 2 * H;
    int j = t * 4;
    float4 w0 = *(const float4*)(wrow + j);
    float4 c0 = *(const float4*)(erow + j);
    float4 w1 = *(const float4*)(wrow + H + j);
    float4 c1 = *(const float4*)(hidden + j);
    float acc = dot4(w0, c0) + dot4(w1, c1);
    acc = warp_sum(acc);
    __shared__ float s[8];
    if ((t & 31) == 0) s[t >> 5] = acc;
    __syncthreads();
    if (t < 8) {
        float v = s[t];
#pragma unroll
        for (int o = 4; o > 0; o >>= 1) v += __shfl_xor_sync(0xffu, v, o);
        if (t == 0) g_attn_logits[l] = v + attn_b[l];
    }
}

// ---- K2: softmax (recomputed per block) + with_attn partial sums ----
__global__ void __launch_bounds__(256) k_with_attn(const float* __restrict__ enc,
                                                   float* __restrict__ out_attn) {
    __shared__ float w[L];
    __shared__ float redm[4], reds[4];
    int t = threadIdx.x;
    float v = 0.f;
    if (t < L) {
        v = g_attn_logits[t];
        float m = v;
#pragma unroll
        for (int o = 16; o > 0; o >>= 1) m = fmaxf(m, __shfl_xor_sync(0xffffffffu, m, o));
        if ((t & 31) == 0) redm[t >> 5] = m;
    }
    __syncthreads();
    float m4 = fmaxf(fmaxf(redm[0], redm[1]), fmaxf(redm[2], redm[3]));
    if (t < L) {
        float e = expf(v - m4);
        float ss = warp_sum(e);
        if ((t & 31) == 0) reds[t >> 5] = ss;
        w[t] = e;
    }
    __syncthreads();
    float tot = (reds[0] + reds[1]) + (reds[2] + reds[3]);
    if (t < L) {
        w[t] = w[t] / tot;
        if (blockIdx.x == 0 && blockIdx.y == 0) out_attn[t] = w[t];
    }
    __syncthreads();
    int col = blockIdx.x * 256 + t;
    int l0 = blockIdx.y * 32;
    float acc0 = 0.f, acc1 = 0.f, acc2 = 0.f, acc3 = 0.f;
#pragma unroll
    for (int l = l0; l < l0 + 32; l += 4) {
        acc0 += w[l + 0] * __ldg(enc + (l + 0) * H + col);
        acc1 += w[l + 1] * __ldg(enc + (l + 1) * H + col);
        acc2 += w[l + 2] * __ldg(enc + (l + 2) * H + col);
        acc3 += w[l + 3] * __ldg(enc + (l + 3) * H + col);
    }
    atomicAdd(&g_with_attn[col], (acc0 + acc1) + (acc2 + acc3));
}

// ---- K3: rnn_in[i] = relu(dot(comb_W[i], [emb[x], with_attn]) + comb_b[i]) ----
// block per row; lane-contiguous float4  (51.7-config, measured 6.5us)
__global__ void __launch_bounds__(256) k_rnn_in(const int* __restrict__ x,
                                                const float* __restrict__ emb,
                                                const float* __restrict__ comb_W,
                                                const float* __restrict__ comb_b) {
    int row = blockIdx.x;        // 0..1023
    int t = threadIdx.x;         // 0..255
    const float* erow = emb + (long long)x[0] * H;
    const float* wrow = comb_W + (long long)row * 2 * H;
    int j = t * 4;
    float4 w0 = *(const float4*)(wrow + j);
    float4 c0 = *(const float4*)(erow + j);
    float4 w1 = *(const float4*)(wrow + H + j);
    float4 c1 = *(const float4*)(g_with_attn + j);
    float acc = dot4(w0, c0) + dot4(w1, c1);
    acc = warp_sum(acc);
    __shared__ float s[8];
    if ((t & 31) == 0) s[t >> 5] = acc;
    __syncthreads();
    if (t < 8) {
        float v = s[t];
#pragma unroll
        for (int o = 4; o > 0; o >>= 1) v += __shfl_xor_sync(0xffu, v, o);
        if (t == 0) g_rnn_in[row] = fmaxf(v + comb_b[row], 0.f);
    }
}

// ---- K4: GRU cell. block i: 12 warps, each half of one of the 6 dots ----
// (51.7-config shape)
__global__ void __launch_bounds__(384) k_gru(const float* __restrict__ hidden,
                                             const float* __restrict__ W_ih,
                                             const float* __restrict__ W_hh,
                                             const float* __restrict__ b_ih,
                                             const float* __restrict__ b_hh,
                                             float* __restrict__ out_h) {
    int i = blockIdx.x;              // hidden index 0..1023
    int w = threadIdx.x >> 5;        // 0..11
    int lane = threadIdx.x & 31;
    int d = w >> 1;                  // dot index 0..5
    int half = w & 1;                // which 512-col half
    int g = (d < 3) ? d : (d - 3);
    const float* row;
    const float* vec;
    if (d < 3) { row = W_ih + (long long)(g * H + i) * H; vec = g_rnn_in; }
    else       { row = W_hh + (long long)(g * H + i) * H; vec = hidden;  }
    int base = half * 512;
    float acc = 0.f;
#pragma unroll
    for (int k = 0; k < 4; k++) {
        int j = base + k * 128 + lane * 4;
        float4 a = *(const float4*)(row + j);
        float4 b = *(const float4*)(vec + j);
        acc += dot4(a, b);
    }
    acc = warp_sum(acc);
    __shared__ float s[12];
    if (lane == 0) s[w] = acc;
    __syncthreads();
    if (threadIdx.x == 0) {
        float d0 = s[0]  + s[1]  + b_ih[0 * H + i];   // ih_r
        float d1 = s[2]  + s[3]  + b_ih[1 * H + i];   // ih_z
        float d2 = s[4]  + s[5]  + b_ih[2 * H + i];   // ih_n
        float d3 = s[6]  + s[7]  + b_hh[0 * H + i];   // hh_r
        float d4 = s[8]  + s[9]  + b_hh[1 * H + i];   // hh_z
        float d5 = s[10] + s[11] + b_hh[2 * H + i];   // hh_n
        float r = 1.f / (1.f + expf(-(d0 + d3)));
        float z = 1.f / (1.f + expf(-(d1 + d4)));
        float n = tanhf(d2 + r * d5);
        float h = (1.f - z) * n + z * hidden[i];
        g_hnew[i] = h;
        out_h[i] = h;
    }
}

// ---- K5: big vocab GEMV (51.7-config, byte-identical) ----
__global__ void __launch_bounds__(256, 2) k_logits(const float* __restrict__ out_W,
                                                   const float* __restrict__ out_b) {
    int lane = threadIdx.x & 31;
    int warp = (blockIdx.x * blockDim.x + threadIdx.x) >> 5;
    int nwarps = (gridDim.x * blockDim.x) >> 5;
    float4 h[8];
#pragma unroll
    for (int k = 0; k < 8; k++)
        h[k] = *(const float4*)(g_hnew + k * 128 + lane * 4);
    float lmax = -INFINITY;
    for (int v0 = warp * 2; v0 < V - 1; v0 += nwarps * 2) {
        const float* row0 = out_W + (long long)v0 * H + lane * 4;
        const float* row1 = row0 + H;
        float4 a0[8], a1[8];
#pragma unroll
        for (int k = 0; k < 8; k++) a0[k] = __ldcs((const float4*)(row0 + k * 128));
#pragma unroll
        for (int k = 0; k < 8; k++) a1[k] = __ldcs((const float4*)(row1 + k * 128));
        float acc0 = 0.f, acc1 = 0.f;
#pragma unroll
        for (int k = 0; k < 8; k++) {
            acc0 += dot4(a0[k], h[k]);
            acc1 += dot4(a1[k], h[k]);
        }
        acc0 = warp_sum(acc0);
        acc1 = warp_sum(acc1);
        if (lane == 0) {
            float lg0 = acc0 + out_b[v0];
            float lg1 = acc1 + out_b[v0 + 1];
            g_logits[v0] = lg0;
            g_logits[v0 + 1] = lg1;
            lmax = fmaxf(lmax, fmaxf(lg0, lg1));
        }
    }
    // tail: last row (V odd) handled by warp 0
    if (warp == 0) {
        int v = V - 1;
        const float* row = out_W + (long long)v * H + lane * 4;
        float acc = 0.f;
#pragma unroll
        for (int k = 0; k < 8; k++)
            acc += dot4(__ldcs((const float4*)(row + k * 128)), h[k]);
        acc = warp_sum(acc);
        if (lane == 0) {
            float lg = acc + out_b[v];
            g_logits[v] = lg;
            lmax = fmaxf(lmax, lg);
        }
    }
    if (lane == 0 && lmax > -INFINITY) {
        atomicMax(&g_max_enc, enc_f(lmax));
    }
}

// ---- K6: fused log-softmax epilogue: sumexp + grid barrier + writeout ----
// 256 blocks, all co-resident; g_bar reset each launch by K1's init block.
__global__ void __launch_bounds__(256) k_logsoftmax(float* __restrict__ out) {
    float gmax = dec_f(g_max_enc);
    int idx = blockIdx.x * blockDim.x + threadIdx.x;
    int stride = gridDim.x * blockDim.x;
    float s = 0.f;
    for (int v = idx; v < V; v += stride) s += expf(g_logits[v] - gmax);
    s = warp_sum(s);
    __shared__ float red[8];
    if ((threadIdx.x & 31) == 0) red[threadIdx.x >> 5] = s;
    __syncthreads();
    if (threadIdx.x == 0) {
        float t = 0.f;
#pragma unroll
        for (int i = 0; i < 8; i++) t += red[i];
        atomicAdd(&g_sumexp, t);
        __threadfence();
        atomicAdd(&g_bar, 1);
        while (atomicAdd(&g_bar, 0) < (int)gridDim.x) { }
    }
    __syncthreads();
    float lse = gmax + logf(g_sumexp);
    for (int v = idx; v < V; v += stride) out[v] = g_logits[v] - lse;
}

extern "C" void kernel_launch(void* const* d_in, const int* in_sizes, int n_in,
                              void* d_out, int out_size) {
    const int*   x       = (const int*)d_in[0];
    const float* hidden  = (const float*)d_in[1];
    const float* enc     = (const float*)d_in[2];
    const float* emb     = (const float*)d_in[3];
    const float* attn_W  = (const float*)d_in[4];
    const float* attn_b  = (const float*)d_in[5];
    const float* comb_W  = (const float*)d_in[6];
    const float* comb_b  = (const float*)d_in[7];
    const float* W_ih    = (const float*)d_in[8];
    const float* W_hh    = (const float*)d_in[9];
    const float* b_ih    = (const float*)d_in[10];
    const float* b_hh    = (const float*)d_in[11];
    const float* out_W   = (const float*)d_in[12];
    const float* out_b   = (const float*)d_in[13];
    float* out = (float*)d_out;   // layout: [logp V][h_new H][attn_w L]

    k_attn_logits<<<L + 1, 256>>>(x, hidden, emb, attn_W, attn_b);
    {
        dim3 g(H / 256, 4);
        k_with_attn<<<g, 256>>>(enc, out + V + H);
    }
    k_rnn_in<<<H, 256>>>(x, emb, comb_W, comb_b);
    k_gru<<<H, 384>>>(hidden, W_ih, W_hh, b_ih, b_hh, out + V);
    k_logits<<<296, 256>>>(out_W, out_b);
    k_logsoftmax<<<256, 256>>>(out);
}